// round 14
// baseline (speedup 1.0000x reference)
#include <cuda_runtime.h>
#include <cuda_fp16.h>
#include <math.h>
#include <stdint.h>

// Problem constants
#define BATCH   4
#define SEQLEN  2048
#define DMODEL  1024
#define NHEAD   16
#define HEADDIM 64
#define MROWS   (BATCH * SEQLEN)   // 8192

// Scratch (device globals: no allocation allowed in kernel_launch)
__device__ float  g_q[(size_t)BATCH * NHEAD * SEQLEN * HEADDIM];   // [B,H,L,hd]
__device__ float  g_k[(size_t)BATCH * NHEAD * SEQLEN * HEADDIM];
__device__ float  g_v[(size_t)BATCH * NHEAD * SEQLEN * HEADDIM];
__device__ __half g_xh[(size_t)MROWS * DMODEL];                    // fp16 x
__device__ __half g_wh[4][(size_t)DMODEL * DMODEL];                // fp16 Wq,Wk,Wv,Wo
__device__ __half g_attn_h[(size_t)MROWS * DMODEL];                // fp16 attn out

// ---------------------------------------------------------------------------
// Helpers
// ---------------------------------------------------------------------------
// pack two f32 into f16x2: lo in lower half, hi in upper half
__device__ __forceinline__ uint32_t pack_f16x2(float lo, float hi) {
    uint32_t r;
    asm("cvt.rn.f16x2.f32 %0, %1, %2;" : "=r"(r) : "f"(hi), "f"(lo));
    return r;
}

__device__ __forceinline__ void mma_f16(float* d, const uint32_t* a,
                                        uint32_t b0, uint32_t b1) {
    asm volatile(
        "mma.sync.aligned.m16n8k16.row.col.f32.f16.f16.f32 "
        "{%0,%1,%2,%3}, {%4,%5,%6,%7}, {%8,%9}, {%0,%1,%2,%3};\n"
        : "+f"(d[0]), "+f"(d[1]), "+f"(d[2]), "+f"(d[3])
        : "r"(a[0]), "r"(a[1]), "r"(a[2]), "r"(a[3]), "r"(b0), "r"(b1));
}

__device__ __forceinline__ void cp_async16(uint32_t smem_addr, const void* gptr) {
    asm volatile("cp.async.ca.shared.global [%0], [%1], 16;\n"
                 :: "r"(smem_addr), "l"(gptr));
}
#define CP_COMMIT() asm volatile("cp.async.commit_group;\n" ::: "memory")

// ---------------------------------------------------------------------------
// fp32 -> fp16 conversion (rn). Each thread converts 4 elements.
// ---------------------------------------------------------------------------
__global__ __launch_bounds__(256) void cvt_f16_kernel(const float* __restrict__ src,
                                                      __half* __restrict__ dst,
                                                      int n4)
{
    int i = blockIdx.x * 256 + threadIdx.x;
    if (i < n4) {
        float4 v = reinterpret_cast<const float4*>(src)[i];
        uint32_t p0 = pack_f16x2(v.x, v.y);
        uint32_t p1 = pack_f16x2(v.z, v.w);
        reinterpret_cast<uint2*>(dst)[i] = make_uint2(p0, p1);
    }
}

// ---------------------------------------------------------------------------
// FP16 GEMM with 4-stage cp.async pipeline.
// C[m,n] = sum_k A[m,k]*W[n,k] + bias[n];  A,W fp16 K-contiguous, acc fp32.
// Block 128x128, BK=32, 256 threads (8 warps 2m x 4n), warp tile 64x32.
// Smem rows: 16 u32 + pad -> stride 20 u32. Dynamic smem: 4 stages x 2
// operands x 128x20 u32 = 81920 B (2 blocks/SM on sm_100a's 227KB).
// ---------------------------------------------------------------------------
#define GTILE_U32 (128 * 20)
#define GSTAGES 4
#define GEMM_SMEM_BYTES (2 * GSTAGES * GTILE_U32 * 4)   // 81920

__global__ __launch_bounds__(256) void gemm_f16(const __half* __restrict__ A_in,
                                                const __half* __restrict__ Wt,
                                                const float* __restrict__ bias,
                                                float* __restrict__ C_out,
                                                int sel)
{
    extern __shared__ uint32_t sm[];
    uint32_t* Asm = sm;                          // GSTAGES tiles
    uint32_t* Wsm = sm + GSTAGES * GTILE_U32;    // GSTAGES tiles

    const int K = DMODEL;
    const __half* A = (sel == 3) ? g_attn_h : A_in;
    float* C;
    if (sel == 0)      C = g_q;
    else if (sel == 1) C = g_k;
    else if (sel == 2) C = g_v;
    else               C = C_out;

    const int tid  = threadIdx.x;
    const int w    = tid >> 5;
    const int lane = tid & 31;
    const int g    = lane >> 2;
    const int q    = lane & 3;
    const int wm   = (w & 1) * 64;
    const int wn   = (w >> 1) * 32;

    const int m0 = blockIdx.y * 128;
    const int n0 = blockIdx.x * 128;

    const __half* Aptr = A  + (size_t)m0 * K;
    const __half* Wptr = Wt + (size_t)n0 * K;

    const uint32_t sA0 = (uint32_t)__cvta_generic_to_shared(Asm);
    const uint32_t sW0 = (uint32_t)__cvta_generic_to_shared(Wsm);

    // copy mapping: 512 16B-chunks per operand; idx = tid + i*256
    int ld_row[2], ld_ch[2];
#pragma unroll
    for (int i = 0; i < 2; i++) {
        int idx = tid + i * 256;
        ld_row[i] = idx >> 2;       // 0..127
        ld_ch[i]  = idx & 3;        // 16B chunk within 64B row
    }

    float acc[4][4][4];
#pragma unroll
    for (int mi = 0; mi < 4; mi++)
#pragma unroll
        for (int nj = 0; nj < 4; nj++)
#pragma unroll
            for (int c = 0; c < 4; c++) acc[mi][nj][c] = 0.0f;

    // Prologue: issue copies for tiles 0..GSTAGES-2
#pragma unroll
    for (int p = 0; p < GSTAGES - 1; p++) {
        int kt = p * 32;
        uint32_t bufo = (uint32_t)(p * GTILE_U32) << 2;
#pragma unroll
        for (int i = 0; i < 2; i++) {
            uint32_t off = bufo + ((uint32_t)(ld_row[i] * 20 + ld_ch[i] * 4) << 2);
            cp_async16(sA0 + off, Aptr + (size_t)ld_row[i] * K + kt + ld_ch[i] * 8);
            cp_async16(sW0 + off, Wptr + (size_t)ld_row[i] * K + kt + ld_ch[i] * 8);
        }
        CP_COMMIT();
    }

    const int NIT = K / 32;   // 32
    for (int it = 0; it < NIT; it++) {
        // Tile `it` complete <=> first it+1 groups done <=> <=2 pending
        // (commits at top of iter it total 3+it, one per iter incl. empties).
        asm volatile("cp.async.wait_group %0;\n" :: "n"(GSTAGES - 2) : "memory");
        __syncthreads();

        // Issue copy for tile it+3 into stage (it+3)%4 (computed at it-1,
        // all warps past the barrier above). Empty commit otherwise.
        if (it + GSTAGES - 1 < NIT) {
            int kt = (it + GSTAGES - 1) * 32;
            uint32_t bufo = (uint32_t)(((it + GSTAGES - 1) % GSTAGES) * GTILE_U32) << 2;
#pragma unroll
            for (int i = 0; i < 2; i++) {
                uint32_t off = bufo + ((uint32_t)(ld_row[i] * 20 + ld_ch[i] * 4) << 2);
                cp_async16(sA0 + off, Aptr + (size_t)ld_row[i] * K + kt + ld_ch[i] * 8);
                cp_async16(sW0 + off, Wptr + (size_t)ld_row[i] * K + kt + ld_ch[i] * 8);
            }
        }
        CP_COMMIT();

        const uint32_t* Ab = Asm + (it % GSTAGES) * GTILE_U32;
        const uint32_t* Wb = Wsm + (it % GSTAGES) * GTILE_U32;
#pragma unroll
        for (int kc = 0; kc < 2; kc++) {
            const int k0 = kc * 8;
            uint32_t a[4][4];
#pragma unroll
            for (int mi = 0; mi < 4; mi++) {
                int r = wm + mi * 16;
                a[mi][0] = Ab[(r + g) * 20 + k0 + q];
                a[mi][1] = Ab[(r + 8 + g) * 20 + k0 + q];
                a[mi][2] = Ab[(r + g) * 20 + k0 + q + 4];
                a[mi][3] = Ab[(r + 8 + g) * 20 + k0 + q + 4];
            }
            uint32_t b[4][2];
#pragma unroll
            for (int nj = 0; nj < 4; nj++) {
                int bn = wn + nj * 8;
                b[nj][0] = Wb[(bn + g) * 20 + k0 + q];
                b[nj][1] = Wb[(bn + g) * 20 + k0 + q + 4];
            }
#pragma unroll
            for (int mi = 0; mi < 4; mi++)
#pragma unroll
                for (int nj = 0; nj < 4; nj++)
                    mma_f16(acc[mi][nj], a[mi], b[nj][0], b[nj][1]);
        }
    }

    float bn_[4][2];
#pragma unroll
    for (int nj = 0; nj < 4; nj++) {
        int cn = n0 + wn + nj * 8 + 2 * q;
        bn_[nj][0] = bias[cn];
        bn_[nj][1] = bias[cn + 1];
    }

#pragma unroll
    for (int nj = 0; nj < 4; nj++) {
        int cn = n0 + wn + nj * 8 + 2 * q;
#pragma unroll
        for (int mi = 0; mi < 4; mi++) {
#pragma unroll
            for (int rr = 0; rr < 2; rr++) {
                int m = m0 + wm + mi * 16 + g + rr * 8;
                float2 v = make_float2(acc[mi][nj][rr * 2 + 0] + bn_[nj][0],
                                       acc[mi][nj][rr * 2 + 1] + bn_[nj][1]);
                if (sel <= 2) {
                    int h_ = cn >> 6;
                    int d_ = cn & 63;
                    int b_ = m >> 11, l_ = m & 2047;
                    *reinterpret_cast<float2*>(
                        C + (((size_t)(b_ * NHEAD + h_)) * SEQLEN + l_) * HEADDIM + d_) = v;
                } else {
                    *reinterpret_cast<float2*>(C + (size_t)m * DMODEL + cn) = v;
                }
            }
        }
    }
}

// ---------------------------------------------------------------------------
// RoPE pre-pass: rotate g_q (with 1/8 scale folded) and g_k in place.
// ---------------------------------------------------------------------------
__global__ __launch_bounds__(256) void rope_kernel()
{
    int idx = blockIdx.x * 256 + threadIdx.x;
    int d  = idx & 31;
    int l  = (idx >> 5) & (SEQLEN - 1);
    int bh = idx >> 16;
    size_t base = ((size_t)bh * SEQLEN + l) * HEADDIM;

    float invf = __expf(-(float)d * (9.210340371976184f / 32.0f));
    float sn, cs;
    sincosf((float)l * invf, &sn, &cs);

    float q1 = g_q[base + d], q2 = g_q[base + d + 32];
    g_q[base + d]      = (q1 * cs - q2 * sn) * 0.125f;
    g_q[base + d + 32] = (q2 * cs + q1 * sn) * 0.125f;

    float k1 = g_k[base + d], k2 = g_k[base + d + 32];
    g_k[base + d]      = k1 * cs - k2 * sn;
    g_k[base + d + 32] = k2 * cs + k1 * sn;
}

// ---------------------------------------------------------------------------
// Flash attention, fp16 mma (m16n8k16, fp32 accum), RoPE precomputed.
// (round-12/13 winning config, unchanged; epilogue writes fp16 g_attn_h)
// ---------------------------------------------------------------------------
__global__ __launch_bounds__(256, 2) void attn_mma_kernel()
{
    __shared__ float smem_all[128 * 68];              // staging 8704 fl (34816 B)
    float (*Qs)[68] = (float(*)[68])smem_all;
    uint32_t* Kb = (uint32_t*)smem_all;               // 64 x 36 u32
    uint32_t* Vb = (uint32_t*)smem_all + 64 * 36;     // 32 x 68 u32

    const int tid  = threadIdx.x;
    const int w    = tid >> 5;
    const int lane = tid & 31;
    const int g    = lane >> 2;
    const int q    = lane & 3;

    const int bh = blockIdx.y;
    const int b_ = bh >> 4;
    const int h_ = bh & 15;
    const int q0 = blockIdx.x * 128;

    const float* Qg = g_q + (size_t)bh * SEQLEN * HEADDIM;
    const float* Kg = g_k + (size_t)bh * SEQLEN * HEADDIM;
    const float* Vg = g_v + (size_t)bh * SEQLEN * HEADDIM;

    // ---- Load Q tile [128][64] (RoPE'd + scaled) into staging ----
#pragma unroll
    for (int i = 0; i < 8; i++) {
        int idx = tid + i * 256;
        int r = idx >> 4;
        int cv = (idx & 15) * 4;
        float4 v = *reinterpret_cast<const float4*>(Qg + (size_t)(q0 + r) * HEADDIM + cv);
        Qs[r][cv + 0] = v.x; Qs[r][cv + 1] = v.y;
        Qs[r][cv + 2] = v.z; Qs[r][cv + 3] = v.w;
    }
    __syncthreads();

    // ---- Extract Q A-fragments as fp16 pairs ----
    uint32_t aq[4][4];
    {
        int row0 = w * 16 + g;
#pragma unroll
        for (int kc = 0; kc < 4; kc++) {
            int c0 = kc * 16 + 2 * q;
            aq[kc][0] = pack_f16x2(Qs[row0][c0],         Qs[row0][c0 + 1]);
            aq[kc][1] = pack_f16x2(Qs[row0 + 8][c0],     Qs[row0 + 8][c0 + 1]);
            aq[kc][2] = pack_f16x2(Qs[row0][c0 + 8],     Qs[row0][c0 + 9]);
            aq[kc][3] = pack_f16x2(Qs[row0 + 8][c0 + 8], Qs[row0 + 8][c0 + 9]);
        }
    }

    float o[8][4];
    float mA = -INFINITY, mB = -INFINITY, lA = 0.0f, lB = 0.0f;
#pragma unroll
    for (int n = 0; n < 8; n++)
#pragma unroll
        for (int c = 0; c < 4; c++) o[n][c] = 0.0f;

    for (int kk = 0; kk < 32; kk++) {
        const int kv0 = kk * 64;
        __syncthreads();

        // ---- K tile -> Kb: pack d-adjacent pairs ----
#pragma unroll
        for (int i = 0; i < 4; i++) {
            int idx = tid + i * 256;
            int r = idx >> 4;
            int j = idx & 15;
            float4 kv = *reinterpret_cast<const float4*>(
                Kg + (size_t)(kv0 + r) * HEADDIM + 4 * j);
            uint32_t p0 = pack_f16x2(kv.x, kv.y);
            uint32_t p1 = pack_f16x2(kv.z, kv.w);
            *reinterpret_cast<uint2*>(&Kb[r * 36 + 2 * j]) = make_uint2(p0, p1);
        }
        // ---- V tile -> Vb: pack row-adjacent pairs ----
#pragma unroll
        for (int i = 0; i < 4; i++) {
            int idx = tid + i * 256;
            int c2 = idx & 31;
            int rp = idx >> 5;
            const float* src = Vg + (size_t)(kv0 + 2 * rp) * HEADDIM + 2 * c2;
            float2 r0v = *reinterpret_cast<const float2*>(src);
            float2 r1v = *reinterpret_cast<const float2*>(src + HEADDIM);
            uint32_t p0 = pack_f16x2(r0v.x, r1v.x);
            uint32_t p1 = pack_f16x2(r0v.y, r1v.y);
            *reinterpret_cast<uint2*>(&Vb[rp * 68 + 2 * c2]) = make_uint2(p0, p1);
        }
        __syncthreads();

        // ---- S = Q . K^T ----
        float s[8][4];
#pragma unroll
        for (int n = 0; n < 8; n++)
#pragma unroll
            for (int c = 0; c < 4; c++) s[n][c] = 0.0f;

#pragma unroll
        for (int n = 0; n < 8; n++) {
#pragma unroll
            for (int kc = 0; kc < 4; kc++) {
                uint32_t b0 = Kb[(n * 8 + g) * 36 + kc * 8 + q];
                uint32_t b1 = Kb[(n * 8 + g) * 36 + kc * 8 + 4 + q];
                mma_f16(s[n], aq[kc], b0, b1);
            }
        }

        // ---- Online softmax ----
        {
            float mxA = -1e30f, mxB = -1e30f;
#pragma unroll
            for (int n = 0; n < 8; n++) {
                mxA = fmaxf(mxA, fmaxf(s[n][0], s[n][1]));
                mxB = fmaxf(mxB, fmaxf(s[n][2], s[n][3]));
            }
            mxA = fmaxf(mxA, __shfl_xor_sync(0xffffffffu, mxA, 1));
            mxA = fmaxf(mxA, __shfl_xor_sync(0xffffffffu, mxA, 2));
            mxB = fmaxf(mxB, __shfl_xor_sync(0xffffffffu, mxB, 1));
            mxB = fmaxf(mxB, __shfl_xor_sync(0xffffffffu, mxB, 2));
            float mnA = fmaxf(mA, mxA);
            float mnB = fmaxf(mB, mxB);
            float cA = __expf(mA - mnA);
            float cB = __expf(mB - mnB);
            float rsA = 0.0f, rsB = 0.0f;
#pragma unroll
            for (int n = 0; n < 8; n++) {
                s[n][0] = __expf(s[n][0] - mnA); rsA += s[n][0];
                s[n][1] = __expf(s[n][1] - mnA); rsA += s[n][1];
                s[n][2] = __expf(s[n][2] - mnB); rsB += s[n][2];
                s[n][3] = __expf(s[n][3] - mnB); rsB += s[n][3];
                o[n][0] *= cA; o[n][1] *= cA;
                o[n][2] *= cB; o[n][3] *= cB;
            }
            rsA += __shfl_xor_sync(0xffffffffu, rsA, 1);
            rsA += __shfl_xor_sync(0xffffffffu, rsA, 2);
            rsB += __shfl_xor_sync(0xffffffffu, rsB, 1);
            rsB += __shfl_xor_sync(0xffffffffu, rsB, 2);
            lA = lA * cA + rsA; mA = mnA;
            lB = lB * cB + rsB; mB = mnB;
        }

        // ---- P A-frags: pack accumulator pairs in-thread ----
        uint32_t ap[4][4];
#pragma unroll
        for (int kc = 0; kc < 4; kc++) {
            ap[kc][0] = pack_f16x2(s[2 * kc][0],     s[2 * kc][1]);
            ap[kc][1] = pack_f16x2(s[2 * kc][2],     s[2 * kc][3]);
            ap[kc][2] = pack_f16x2(s[2 * kc + 1][0], s[2 * kc + 1][1]);
            ap[kc][3] = pack_f16x2(s[2 * kc + 1][2], s[2 * kc + 1][3]);
        }

        // ---- O += P . V ----
#pragma unroll
        for (int n = 0; n < 8; n++) {
#pragma unroll
            for (int kc = 0; kc < 4; kc++) {
                uint32_t b0 = Vb[(kc * 8 + q) * 68 + n * 8 + g];
                uint32_t b1 = Vb[(kc * 8 + 4 + q) * 68 + n * 8 + g];
                mma_f16(o[n], ap[kc], b0, b1);
            }
        }
    }

    // ---- Epilogue: normalize, write fp16 [B,L,H*hd] ----
    {
        float iA = 1.0f / lA;
        float iB = 1.0f / lB;
        int row0 = q0 + w * 16 + g;
#pragma unroll
        for (int n = 0; n < 8; n++) {
            int col = n * 8 + 2 * q;
            uint32_t p0 = pack_f16x2(o[n][0] * iA, o[n][1] * iA);
            uint32_t p1 = pack_f16x2(o[n][2] * iB, o[n][3] * iB);
            *reinterpret_cast<uint32_t*>(
                g_attn_h + ((size_t)(b_ * SEQLEN + row0) * NHEAD + h_) * HEADDIM + col) = p0;
            *reinterpret_cast<uint32_t*>(
                g_attn_h + ((size_t)(b_ * SEQLEN + row0 + 8) * NHEAD + h_) * HEADDIM + col) = p1;
        }
    }
}

// ---------------------------------------------------------------------------
extern "C" void kernel_launch(void* const* d_in, const int* in_sizes, int n_in,
                              void* d_out, int out_size)
{
    const float* x  = (const float*)d_in[0];
    const float* Wq = (const float*)d_in[1];
    const float* bq = (const float*)d_in[2];
    const float* Wk = (const float*)d_in[3];
    const float* bk = (const float*)d_in[4];
    const float* Wv = (const float*)d_in[5];
    const float* bv = (const float*)d_in[6];
    const float* Wo = (const float*)d_in[7];
    const float* bo = (const float*)d_in[8];
    float* out = (float*)d_out;

    __half* d_xh;     cudaGetSymbolAddress((void**)&d_xh, g_xh);
    __half* d_wh;     cudaGetSymbolAddress((void**)&d_wh, g_wh);

    cudaFuncSetAttribute(gemm_f16,
                         cudaFuncAttributeMaxDynamicSharedMemorySize,
                         GEMM_SMEM_BYTES);

    // fp16 conversions
    const int XN4 = MROWS * DMODEL / 4;          // 2097152
    const int WN4 = DMODEL * DMODEL / 4;         // 262144
    cvt_f16_kernel<<<XN4 / 256, 256>>>(x,  d_xh, XN4);
    cvt_f16_kernel<<<WN4 / 256, 256>>>(Wq, d_wh + 0 * (size_t)DMODEL * DMODEL, WN4);
    cvt_f16_kernel<<<WN4 / 256, 256>>>(Wk, d_wh + 1 * (size_t)DMODEL * DMODEL, WN4);
    cvt_f16_kernel<<<WN4 / 256, 256>>>(Wv, d_wh + 2 * (size_t)DMODEL * DMODEL, WN4);
    cvt_f16_kernel<<<WN4 / 256, 256>>>(Wo, d_wh + 3 * (size_t)DMODEL * DMODEL, WN4);

    dim3 ggrid(DMODEL / 128, MROWS / 128);   // (8, 64)
    gemm_f16<<<ggrid, 256, GEMM_SMEM_BYTES>>>(d_xh, d_wh + 0 * (size_t)DMODEL * DMODEL, bq, nullptr, 0);
    gemm_f16<<<ggrid, 256, GEMM_SMEM_BYTES>>>(d_xh, d_wh + 1 * (size_t)DMODEL * DMODEL, bk, nullptr, 1);
    gemm_f16<<<ggrid, 256, GEMM_SMEM_BYTES>>>(d_xh, d_wh + 2 * (size_t)DMODEL * DMODEL, bv, nullptr, 2);

    rope_kernel<<<(BATCH * NHEAD * SEQLEN * 32) / 256, 256>>>();

    attn_mma_kernel<<<dim3(SEQLEN / 128, BATCH * NHEAD), 256>>>();

    gemm_f16<<<ggrid, 256, GEMM_SMEM_BYTES>>>(nullptr, d_wh + 3 * (size_t)DMODEL * DMODEL, bo, out, 3);
}